// round 2
// baseline (speedup 1.0000x reference)
#include <cuda_runtime.h>
#include <cstdint>

// ---------------------------------------------------------------------------
// f32x2 packed helpers (FFMA2 only reachable via PTX fma.rn.f32x2)
// ---------------------------------------------------------------------------
__device__ __forceinline__ unsigned long long pack2(float lo, float hi) {
    unsigned long long r;
    asm("mov.b64 %0, {%1, %2};" : "=l"(r) : "f"(lo), "f"(hi));
    return r;
}
__device__ __forceinline__ void unpack2(float& lo, float& hi,
                                        unsigned long long v) {
    asm("mov.b64 {%0, %1}, %2;" : "=f"(lo), "=f"(hi) : "l"(v));
}
__device__ __forceinline__ void ffma2(unsigned long long& d,
                                      unsigned long long a,
                                      unsigned long long b) {
    asm("fma.rn.f32x2 %0, %1, %2, %0;" : "+l"(d) : "l"(a), "l"(b));
}
__device__ __forceinline__ float tanh_fast(float x) {
    float y;
    asm("tanh.approx.f32 %0, %1;" : "=f"(y) : "f"(x));
    return y;
}

// Shared pool (floats). Max user: SS path = 2 * 32 * 132 = 8448.
// MLP path: As(32*68) Bs(32*68) Xs(64*36) W(32*33) sw(33) = 7745.
#define POOL_FLOATS 8448

// ---------------------------------------------------------------------------
// Inline projection pass (MLP tiles): dst[d][row] = 0.5*(X[row,:]@W[:,d] + b1d)
// dst is k-major [32][68]. 256 threads; each computes 8 (row,d) outputs.
// ---------------------------------------------------------------------------
__device__ __forceinline__ void proj_pass(const float* __restrict__ src,
                                          const float* __restrict__ w,
                                          const float* __restrict__ b1,
                                          float* Xs, float* W, float* dst,
                                          int tid) {
    // Load 64x32 inputs (stride 36 keeps float4 alignment) + 32x32 weights.
    for (int l = tid; l < 512; l += 256) {
        const int row = l >> 3;
        const int c = (l & 7) << 2;
        const float4 v = *(const float4*)(src + row * 32 + c);
        *(float4*)(Xs + row * 36 + c) = v;
    }
    for (int l = tid; l < 1024; l += 256) W[(l >> 5) * 33 + (l & 31)] = w[l];
    __syncthreads();

    const int d = tid & 31;
    const int rg = tid >> 5;
    const float bv = b1 ? b1[d] : 0.f;
#pragma unroll
    for (int j = 0; j < 8; j++) {
        const int row = rg * 8 + j;
        float acc = bv;
#pragma unroll
        for (int f = 0; f < 32; f++)
            acc = fmaf(Xs[row * 36 + f], W[f * 33 + d], acc);
        dst[d * 68 + row] = 0.5f * acc;
    }
    __syncthreads();
}

// ---------------------------------------------------------------------------
// Single fused kernel. Per batch: 97 blocks.
//   r % 3 == 0 -> s = r/3: s<16 ST tile (64x64), s<32 TS tile, s==32 TT gram.
//   else       -> g = r - r/3 - 1 in [0,64): SS gram 128x128 tile (ti=g>>3).
// ---------------------------------------------------------------------------
__global__ __launch_bounds__(256, 2) void adj_fused_kernel(
    const float* __restrict__ spatial, const float* __restrict__ temporal,
    const float* __restrict__ st_w1, const float* __restrict__ st_b1,
    const float* __restrict__ st_w2, const float* __restrict__ st_b2,
    const float* __restrict__ ts_w1, const float* __restrict__ ts_b1,
    const float* __restrict__ ts_w2, const float* __restrict__ ts_b2,
    float* __restrict__ out) {
    __shared__ float pool[POOL_FLOATS];

    const int b = blockIdx.x / 97;
    const int r = blockIdx.x % 97;
    const int tid = threadIdx.x;

    if (r % 3 != 0) {
        // ================= SS gram: 128x128 tile, 8x8 per thread, FFMA2 ====
        const int g = r - r / 3 - 1;
        const int ti = g >> 3;
        const int tj = g & 7;
        float* As = pool;              // [32][132] k-major
        float* Bs = pool + 32 * 132;

        const float* Asrc = spatial + ((size_t)b * 1024 + ti * 128) * 32;
        const float* Bsrc = spatial + ((size_t)b * 1024 + tj * 128) * 32;
        for (int l = tid; l < 1024; l += 256) {
            const int row = l >> 3;
            const int kq = (l & 7) << 2;
            const float4 va = *(const float4*)(Asrc + row * 32 + kq);
            As[(kq + 0) * 132 + row] = va.x;
            As[(kq + 1) * 132 + row] = va.y;
            As[(kq + 2) * 132 + row] = va.z;
            As[(kq + 3) * 132 + row] = va.w;
            const float4 vb = *(const float4*)(Bsrc + row * 32 + kq);
            Bs[(kq + 0) * 132 + row] = vb.x;
            Bs[(kq + 1) * 132 + row] = vb.y;
            Bs[(kq + 2) * 132 + row] = vb.z;
            Bs[(kq + 3) * 132 + row] = vb.w;
        }
        __syncthreads();

        const int tx = tid & 15;  // j-tile
        const int ty = tid >> 4;  // i-tile
        unsigned long long acc[8][4];
#pragma unroll
        for (int i = 0; i < 8; i++)
#pragma unroll
            for (int jp = 0; jp < 4; jp++) acc[i][jp] = 0ull;

        const float* Ap = As + ty * 8;
        const float* Bp = Bs + tx * 8;
#pragma unroll
        for (int k = 0; k < 32; k++) {
            const float4 a0 = *(const float4*)(Ap + k * 132);
            const float4 a1 = *(const float4*)(Ap + k * 132 + 4);
            const float4 b0 = *(const float4*)(Bp + k * 132);
            const float4 b1v = *(const float4*)(Bp + k * 132 + 4);
            unsigned long long bp[4];
            bp[0] = pack2(b0.x, b0.y);
            bp[1] = pack2(b0.z, b0.w);
            bp[2] = pack2(b1v.x, b1v.y);
            bp[3] = pack2(b1v.z, b1v.w);
            const float av[8] = {a0.x, a0.y, a0.z, a0.w,
                                 a1.x, a1.y, a1.z, a1.w};
#pragma unroll
            for (int i = 0; i < 8; i++) {
                const unsigned long long ad = pack2(av[i], av[i]);
#pragma unroll
                for (int jp = 0; jp < 4; jp++) ffma2(acc[i][jp], ad, bp[jp]);
            }
        }

        float* ob = out + ((size_t)b * 1088 + ti * 128 + ty * 8) * 1088 +
                    tj * 128 + tx * 8;
#pragma unroll
        for (int i = 0; i < 8; i++) {
            float v[8];
#pragma unroll
            for (int jp = 0; jp < 4; jp++)
                unpack2(v[2 * jp], v[2 * jp + 1], acc[i][jp]);
            float4 o0, o1;
            o0.x = tanh_fast(fmaxf(v[0], 0.f));
            o0.y = tanh_fast(fmaxf(v[1], 0.f));
            o0.z = tanh_fast(fmaxf(v[2], 0.f));
            o0.w = tanh_fast(fmaxf(v[3], 0.f));
            o1.x = tanh_fast(fmaxf(v[4], 0.f));
            o1.y = tanh_fast(fmaxf(v[5], 0.f));
            o1.z = tanh_fast(fmaxf(v[6], 0.f));
            o1.w = tanh_fast(fmaxf(v[7], 0.f));
            *(float4*)(ob + (size_t)i * 1088) = o0;
            *(float4*)(ob + (size_t)i * 1088 + 4) = o1;
        }
        return;
    }

    // ==================== MLP (ST / TS) and TT gram: 64x64 tiles ===========
    const int s = r / 3;
    float* As = pool;               // [32][68] k-major
    float* Bs = pool + 32 * 68;
    float* Xs = pool + 2 * 32 * 68;                 // [64][36]
    float* W = pool + 2 * 32 * 68 + 64 * 36;        // [32][33]
    float* sw = pool + 2 * 32 * 68 + 64 * 36 + 32 * 33;  // [33]

    int gi0, gj0;
    const bool isGram = (s == 32);

    if (isGram) {
        // TT gram: temporal x temporal (64x64).
        const float* Tsrc = temporal + (size_t)b * 64 * 32;
        for (int l = tid; l < 512; l += 256) {
            const int row = l >> 3;
            const int kq = (l & 7) << 2;
            const float4 v = *(const float4*)(Tsrc + row * 32 + kq);
            As[(kq + 0) * 68 + row] = v.x;
            As[(kq + 1) * 68 + row] = v.y;
            As[(kq + 2) * 68 + row] = v.z;
            As[(kq + 3) * 68 + row] = v.w;
            Bs[(kq + 0) * 68 + row] = v.x;
            Bs[(kq + 1) * 68 + row] = v.y;
            Bs[(kq + 2) * 68 + row] = v.z;
            Bs[(kq + 3) * 68 + row] = v.w;
        }
        __syncthreads();
        gi0 = 1024;
        gj0 = 1024;
    } else {
        const bool isST = (s < 16);
        const float* w1 = isST ? st_w1 : ts_w1;
        const float* b1 = isST ? st_b1 : ts_b1;
        const float* w2 = isST ? st_w2 : ts_w2;
        const float* b2 = isST ? st_b2 : ts_b2;
        // a-side rows (tile rows), b-side rows (tile cols)
        const float* asrc;
        const float* bsrc;
        if (isST) {  // rows = spatial chunk s, cols = temporal
            asrc = spatial + ((size_t)b * 1024 + s * 64) * 32;
            bsrc = temporal + (size_t)b * 64 * 32;
            gi0 = s * 64;
            gj0 = 1024;
        } else {  // TS: rows = temporal, cols = spatial chunk s-16
            asrc = temporal + (size_t)b * 64 * 32;
            bsrc = spatial + ((size_t)b * 1024 + (s - 16) * 64) * 32;
            gi0 = 1024;
            gj0 = (s - 16) * 64;
        }

        if (tid < 32) sw[tid] = 0.5f * w2[tid];
        // Pass A: a' = 0.5*(asrc @ w1[:32] + b1)   (first sync covers sw)
        proj_pass(asrc, w1, b1, Xs, W, As, tid);
        if (tid == 0) {
            float c = b2[0];
#pragma unroll
            for (int k = 0; k < 32; k++) c += sw[k];
            sw[32] = c;
        }
        // Pass B: b' = 0.5*(bsrc @ w1[32:])  (its first sync covers sw[32])
        proj_pass(bsrc, w1 + 1024, nullptr, Xs, W, Bs, tid);
    }

    const int tx = tid & 15;
    const int ty = tid >> 4;
    float acc[4][4];
#pragma unroll
    for (int i = 0; i < 4; i++)
#pragma unroll
        for (int j = 0; j < 4; j++) acc[i][j] = 0.f;

    const float* ap = As + ty * 4;
    const float* bp = Bs + tx * 4;

    if (isGram) {
#pragma unroll
        for (int k = 0; k < 32; k++) {
            const float4 a = *(const float4*)(ap + k * 68);
            const float4 bb = *(const float4*)(bp + k * 68);
            const float av[4] = {a.x, a.y, a.z, a.w};
            const float bv[4] = {bb.x, bb.y, bb.z, bb.w};
#pragma unroll
            for (int i = 0; i < 4; i++)
#pragma unroll
                for (int j = 0; j < 4; j++)
                    acc[i][j] = fmaf(av[i], bv[j], acc[i][j]);
        }
    } else {
#pragma unroll
        for (int k = 0; k < 32; k++) {
            const float4 a = *(const float4*)(ap + k * 68);
            const float4 bb = *(const float4*)(bp + k * 68);
            const float av[4] = {a.x, a.y, a.z, a.w};
            const float bv[4] = {bb.x, bb.y, bb.z, bb.w};
            const float w = sw[k];
#pragma unroll
            for (int i = 0; i < 4; i++)
#pragma unroll
                for (int j = 0; j < 4; j++) {
                    const float t = tanh_fast(av[i] + bv[j]);
                    acc[i][j] = fmaf(t, w, acc[i][j]);
                }
        }
        const float c0 = sw[32];
#pragma unroll
        for (int i = 0; i < 4; i++)
#pragma unroll
            for (int j = 0; j < 4; j++) acc[i][j] += c0;
    }

    float* ob = out + ((size_t)b * 1088 + gi0 + ty * 4) * 1088 + gj0 + tx * 4;
#pragma unroll
    for (int i = 0; i < 4; i++) {
        float4 v;
        v.x = tanh_fast(fmaxf(acc[i][0], 0.f));
        v.y = tanh_fast(fmaxf(acc[i][1], 0.f));
        v.z = tanh_fast(fmaxf(acc[i][2], 0.f));
        v.w = tanh_fast(fmaxf(acc[i][3], 0.f));
        *(float4*)(ob + (size_t)i * 1088) = v;
    }
}

extern "C" void kernel_launch(void* const* d_in, const int* in_sizes, int n_in,
                              void* d_out, int out_size) {
    const float* spatial = (const float*)d_in[0];   // [32,1024,32]
    const float* temporal = (const float*)d_in[1];  // [32,64,32]
    const float* st_w1 = (const float*)d_in[2];     // [64,32]
    const float* st_b1 = (const float*)d_in[3];     // [32]
    const float* st_w2 = (const float*)d_in[4];     // [32,1]
    const float* st_b2 = (const float*)d_in[5];     // [1]
    const float* ts_w1 = (const float*)d_in[6];
    const float* ts_b1 = (const float*)d_in[7];
    const float* ts_w2 = (const float*)d_in[8];
    const float* ts_b2 = (const float*)d_in[9];
    float* out = (float*)d_out;                     // [32,1088,1088]

    adj_fused_kernel<<<32 * 97, 256>>>(spatial, temporal, st_w1, st_b1, st_w2,
                                       st_b2, ts_w1, ts_b1, ts_w2, ts_b2, out);
}

// round 4
// speedup vs baseline: 1.1748x; 1.1748x over previous
#include <cuda_runtime.h>
#include <cstdint>

// ---------------------------------------------------------------------------
// f32x2 packed helpers (FFMA2 only reachable via PTX fma.rn.f32x2)
// ---------------------------------------------------------------------------
__device__ __forceinline__ unsigned long long pack2(float lo, float hi) {
    unsigned long long r;
    asm("mov.b64 %0, {%1, %2};" : "=l"(r) : "f"(lo), "f"(hi));
    return r;
}
__device__ __forceinline__ void unpack2(float& lo, float& hi,
                                        unsigned long long v) {
    asm("mov.b64 {%0, %1}, %2;" : "=f"(lo), "=f"(hi) : "l"(v));
}
__device__ __forceinline__ void ffma2(unsigned long long& d,
                                      unsigned long long a,
                                      unsigned long long b) {
    asm("fma.rn.f32x2 %0, %1, %2, %0;" : "+l"(d) : "l"(a), "l"(b));
}
__device__ __forceinline__ float tanh_fast(float x) {
    float y;
    asm("tanh.approx.f32 %0, %1;" : "=f"(y) : "f"(x));
    return y;
}

// Shared pool (floats).
// SS path:  As/Bs = 2*32*132 = 8448, bounce reuse = 64*133 = 8512.
// MLP path: As(32*68)+Bs(32*68)+Xs(64*36)+W(32*33)+sw(33) = 7745.
#define POOL_FLOATS 8512

// ---------------------------------------------------------------------------
// Inline projection pass (MLP tiles): dst[d][row] = 0.5*(X[row,:]@W[:,d]+b1d)
// dst is k-major [32][68]. 256 threads.
// ---------------------------------------------------------------------------
__device__ __forceinline__ void proj_pass(const float* __restrict__ src,
                                          const float* __restrict__ w,
                                          const float* __restrict__ b1,
                                          float* Xs, float* W, float* dst,
                                          int tid) {
    for (int l = tid; l < 512; l += 256) {
        const int row = l >> 3;
        const int c = (l & 7) << 2;
        const float4 v = *(const float4*)(src + row * 32 + c);
        *(float4*)(Xs + row * 36 + c) = v;
    }
    for (int l = tid; l < 1024; l += 256) W[(l >> 5) * 33 + (l & 31)] = w[l];
    __syncthreads();

    const int d = tid & 31;
    const int rg = tid >> 5;
    const float bv = b1 ? b1[d] : 0.f;
#pragma unroll
    for (int j = 0; j < 8; j++) {
        const int row = rg * 8 + j;
        float acc = bv;
#pragma unroll
        for (int f = 0; f < 32; f++)
            acc = fmaf(Xs[row * 36 + f], W[f * 33 + d], acc);
        dst[d * 68 + row] = 0.5f * acc;
    }
    __syncthreads();
}

// ---------------------------------------------------------------------------
// Fused kernel. 72 block-slots per batch:
//   r even -> s = r/2 < 36 : SS gram 128x128 triangular tile (ti<=tj),
//             mirror tile written via smem-bounce transpose.
//   r odd  -> m = r/2 : m<16 ST (64x64), m<32 TS, m==32 TT gram, else idle.
// ---------------------------------------------------------------------------
__global__ __launch_bounds__(256, 2) void adj_fused_kernel(
    const float* __restrict__ spatial, const float* __restrict__ temporal,
    const float* __restrict__ st_w1, const float* __restrict__ st_b1,
    const float* __restrict__ st_w2, const float* __restrict__ st_b2,
    const float* __restrict__ ts_w1, const float* __restrict__ ts_b1,
    const float* __restrict__ ts_w2, const float* __restrict__ ts_b2,
    float* __restrict__ out) {
    __shared__ float pool[POOL_FLOATS];

    const int b = blockIdx.x / 72;
    const int r = blockIdx.x % 72;
    const int tid = threadIdx.x;

    if ((r & 1) == 0) {
        // ============ SS gram: triangular 128x128 tile, 8x8 FFMA2 ==========
        const int s = r >> 1;  // 0..35
        int ti = 0, rem = s;
#pragma unroll
        for (int t = 0; t < 8; t++) {
            if (rem >= 8 - ti) { rem -= 8 - ti; ti++; }
        }
        const int tj = ti + rem;

        float* As = pool;               // [32][132] k-major
        float* Bs = pool + 32 * 132;

        const float* Asrc = spatial + ((size_t)b * 1024 + ti * 128) * 32;
        const float* Bsrc = spatial + ((size_t)b * 1024 + tj * 128) * 32;
        for (int l = tid; l < 1024; l += 256) {
            const int row = l >> 3;
            const int kq = (l & 7) << 2;
            const float4 va = *(const float4*)(Asrc + row * 32 + kq);
            As[(kq + 0) * 132 + row] = va.x;
            As[(kq + 1) * 132 + row] = va.y;
            As[(kq + 2) * 132 + row] = va.z;
            As[(kq + 3) * 132 + row] = va.w;
            const float4 vb = *(const float4*)(Bsrc + row * 32 + kq);
            Bs[(kq + 0) * 132 + row] = vb.x;
            Bs[(kq + 1) * 132 + row] = vb.y;
            Bs[(kq + 2) * 132 + row] = vb.z;
            Bs[(kq + 3) * 132 + row] = vb.w;
        }
        __syncthreads();

        const int tx = tid & 15;  // j-tile 0..15
        const int ty = tid >> 4;  // i-tile 0..15
        unsigned long long acc[8][4];
#pragma unroll
        for (int i = 0; i < 8; i++)
#pragma unroll
            for (int jp = 0; jp < 4; jp++) acc[i][jp] = 0ull;

        const float* Ap = As + ty * 8;
        const float* Bp = Bs + tx * 8;

        // Software-pipelined mainloop: prefetch k+1 while computing k.
        float4 a0 = *(const float4*)(Ap);
        float4 a1 = *(const float4*)(Ap + 4);
        float4 b0 = *(const float4*)(Bp);
        float4 b1v = *(const float4*)(Bp + 4);
#pragma unroll
        for (int k = 0; k < 32; k++) {
            float4 na0, na1, nb0, nb1;
            if (k < 31) {
                na0 = *(const float4*)(Ap + (k + 1) * 132);
                na1 = *(const float4*)(Ap + (k + 1) * 132 + 4);
                nb0 = *(const float4*)(Bp + (k + 1) * 132);
                nb1 = *(const float4*)(Bp + (k + 1) * 132 + 4);
            }
            unsigned long long bp[4];
            bp[0] = pack2(b0.x, b0.y);
            bp[1] = pack2(b0.z, b0.w);
            bp[2] = pack2(b1v.x, b1v.y);
            bp[3] = pack2(b1v.z, b1v.w);
            const float av[8] = {a0.x, a0.y, a0.z, a0.w,
                                 a1.x, a1.y, a1.z, a1.w};
#pragma unroll
            for (int i = 0; i < 8; i++) {
                const unsigned long long ad = pack2(av[i], av[i]);
#pragma unroll
                for (int jp = 0; jp < 4; jp++) ffma2(acc[i][jp], ad, bp[jp]);
            }
            a0 = na0; a1 = na1; b0 = nb0; b1v = nb1;
        }

        // Epilogue: activate, store normal tile, keep activated in acc.
        float* ob = out + ((size_t)b * 1088 + ti * 128 + ty * 8) * 1088 +
                    tj * 128 + tx * 8;
#pragma unroll
        for (int i = 0; i < 8; i++) {
            float v[8];
#pragma unroll
            for (int jp = 0; jp < 4; jp++)
                unpack2(v[2 * jp], v[2 * jp + 1], acc[i][jp]);
#pragma unroll
            for (int j = 0; j < 8; j++) v[j] = tanh_fast(fmaxf(v[j], 0.f));
            float4 o0 = {v[0], v[1], v[2], v[3]};
            float4 o1 = {v[4], v[5], v[6], v[7]};
            *(float4*)(ob + (size_t)i * 1088) = o0;
            *(float4*)(ob + (size_t)i * 1088 + 4) = o1;
#pragma unroll
            for (int jp = 0; jp < 4; jp++)
                acc[i][jp] = pack2(v[2 * jp], v[2 * jp + 1]);
        }

        if (ti == tj) return;  // diagonal: no mirror

        // Mirror tile (tj,ti) via smem-bounce transpose, two 64-row passes.
        // Stride 133: conflict-mitigated writes; drain is SCALAR (stride-1
        // cols per lane -> conflict-free LDS.32 + coalesced STG.32). float4
        // here would be misaligned (133 % 4 != 0) -- caused the R3 trap.
        float* bounce = pool;  // [64][133]
#pragma unroll
        for (int p = 0; p < 2; p++) {
            __syncthreads();  // pool free / previous pass consumed
            if ((tx >> 3) == p) {
                const int rb = (tx & 7) * 8;  // local mirror-row base
#pragma unroll
                for (int jj = 0; jj < 8; jj++) {
#pragma unroll
                    for (int ii = 0; ii < 8; ii++) {
                        float lo, hi;
                        unpack2(lo, hi, acc[ii][jj >> 1]);
                        bounce[(rb + jj) * 133 + ty * 8 + ii] =
                            (jj & 1) ? hi : lo;
                    }
                }
            }
            __syncthreads();
            // Scalar drain: 64 rows x 128 cols, 32 elems/thread.
            float* od =
                out + ((size_t)b * 1088 + tj * 128 + p * 64) * 1088 + ti * 128;
            for (int l = tid; l < 64 * 128; l += 256) {
                const int row = l >> 7;
                const int col = l & 127;
                od[(size_t)row * 1088 + col] = bounce[row * 133 + col];
            }
        }
        return;
    }

    // ==================== MLP (ST / TS) and TT gram: 64x64 tiles ===========
    const int m = r >> 1;
    if (m > 32) return;  // idle slots
    float* As = pool;               // [32][68] k-major
    float* Bs = pool + 32 * 68;
    float* Xs = pool + 2 * 32 * 68;                      // [64][36]
    float* W = pool + 2 * 32 * 68 + 64 * 36;             // [32][33]
    float* sw = pool + 2 * 32 * 68 + 64 * 36 + 32 * 33;  // [33]

    int gi0, gj0;
    const bool isGram = (m == 32);

    if (isGram) {
        const float* Tsrc = temporal + (size_t)b * 64 * 32;
        for (int l = tid; l < 512; l += 256) {
            const int row = l >> 3;
            const int kq = (l & 7) << 2;
            const float4 v = *(const float4*)(Tsrc + row * 32 + kq);
            As[(kq + 0) * 68 + row] = v.x;
            As[(kq + 1) * 68 + row] = v.y;
            As[(kq + 2) * 68 + row] = v.z;
            As[(kq + 3) * 68 + row] = v.w;
            Bs[(kq + 0) * 68 + row] = v.x;
            Bs[(kq + 1) * 68 + row] = v.y;
            Bs[(kq + 2) * 68 + row] = v.z;
            Bs[(kq + 3) * 68 + row] = v.w;
        }
        __syncthreads();
        gi0 = 1024;
        gj0 = 1024;
    } else {
        const bool isST = (m < 16);
        const float* w1 = isST ? st_w1 : ts_w1;
        const float* b1 = isST ? st_b1 : ts_b1;
        const float* w2 = isST ? st_w2 : ts_w2;
        const float* b2 = isST ? st_b2 : ts_b2;
        const float* asrc;
        const float* bsrc;
        if (isST) {
            asrc = spatial + ((size_t)b * 1024 + m * 64) * 32;
            bsrc = temporal + (size_t)b * 64 * 32;
            gi0 = m * 64;
            gj0 = 1024;
        } else {
            asrc = temporal + (size_t)b * 64 * 32;
            bsrc = spatial + ((size_t)b * 1024 + (m - 16) * 64) * 32;
            gi0 = 1024;
            gj0 = (m - 16) * 64;
        }

        if (tid < 32) sw[tid] = 0.5f * w2[tid];
        proj_pass(asrc, w1, b1, Xs, W, As, tid);  // a' (sync covers sw)
        if (tid == 0) {
            float c = b2[0];
#pragma unroll
            for (int k = 0; k < 32; k++) c += sw[k];
            sw[32] = c;
        }
        proj_pass(bsrc, w1 + 1024, nullptr, Xs, W, Bs, tid);  // b'
    }

    const int tx = tid & 15;
    const int ty = tid >> 4;
    float acc[4][4];
#pragma unroll
    for (int i = 0; i < 4; i++)
#pragma unroll
        for (int j = 0; j < 4; j++) acc[i][j] = 0.f;

    const float* ap = As + ty * 4;
    const float* bp = Bs + tx * 4;

    if (isGram) {
#pragma unroll
        for (int k = 0; k < 32; k++) {
            const float4 a = *(const float4*)(ap + k * 68);
            const float4 bb = *(const float4*)(bp + k * 68);
            const float av[4] = {a.x, a.y, a.z, a.w};
            const float bv[4] = {bb.x, bb.y, bb.z, bb.w};
#pragma unroll
            for (int i = 0; i < 4; i++)
#pragma unroll
                for (int j = 0; j < 4; j++)
                    acc[i][j] = fmaf(av[i], bv[j], acc[i][j]);
        }
    } else {
#pragma unroll
        for (int k = 0; k < 32; k++) {
            const float4 a = *(const float4*)(ap + k * 68);
            const float4 bb = *(const float4*)(bp + k * 68);
            const float av[4] = {a.x, a.y, a.z, a.w};
            const float bv[4] = {bb.x, bb.y, bb.z, bb.w};
            const float w = sw[k];
#pragma unroll
            for (int i = 0; i < 4; i++)
#pragma unroll
                for (int j = 0; j < 4; j++) {
                    const float t = tanh_fast(av[i] + bv[j]);
                    acc[i][j] = fmaf(t, w, acc[i][j]);
                }
        }
        const float c0 = sw[32];
#pragma unroll
        for (int i = 0; i < 4; i++)
#pragma unroll
            for (int j = 0; j < 4; j++) acc[i][j] += c0;
    }

    float* ob = out + ((size_t)b * 1088 + gi0 + ty * 4) * 1088 + gj0 + tx * 4;
#pragma unroll
    for (int i = 0; i < 4; i++) {
        float4 v;
        v.x = tanh_fast(fmaxf(acc[i][0], 0.f));
        v.y = tanh_fast(fmaxf(acc[i][1], 0.f));
        v.z = tanh_fast(fmaxf(acc[i][2], 0.f));
        v.w = tanh_fast(fmaxf(acc[i][3], 0.f));
        *(float4*)(ob + (size_t)i * 1088) = v;
    }
}

extern "C" void kernel_launch(void* const* d_in, const int* in_sizes, int n_in,
                              void* d_out, int out_size) {
    const float* spatial = (const float*)d_in[0];   // [32,1024,32]
    const float* temporal = (const float*)d_in[1];  // [32,64,32]
    const float* st_w1 = (const float*)d_in[2];     // [64,32]
    const float* st_b1 = (const float*)d_in[3];     // [32]
    const float* st_w2 = (const float*)d_in[4];     // [32,1]
    const float* st_b2 = (const float*)d_in[5];     // [1]
    const float* ts_w1 = (const float*)d_in[6];
    const float* ts_b1 = (const float*)d_in[7];
    const float* ts_w2 = (const float*)d_in[8];
    const float* ts_b2 = (const float*)d_in[9];
    float* out = (float*)d_out;                     // [32,1088,1088]

    adj_fused_kernel<<<32 * 72, 256>>>(spatial, temporal, st_w1, st_b1, st_w2,
                                       st_b2, ts_w1, ts_b1, ts_w2, ts_b2, out);
}

// round 5
// speedup vs baseline: 1.3128x; 1.1175x over previous
#include <cuda_runtime.h>
#include <cstdint>

// ---------------------------------------------------------------------------
// f32x2 packed helpers (FFMA2 only reachable via PTX fma.rn.f32x2)
// ---------------------------------------------------------------------------
__device__ __forceinline__ unsigned long long pack2(float lo, float hi) {
    unsigned long long r;
    asm("mov.b64 %0, {%1, %2};" : "=l"(r) : "f"(lo), "f"(hi));
    return r;
}
__device__ __forceinline__ void unpack2(float& lo, float& hi,
                                        unsigned long long v) {
    asm("mov.b64 {%0, %1}, %2;" : "=f"(lo), "=f"(hi) : "l"(v));
}
__device__ __forceinline__ void ffma2(unsigned long long& d,
                                      unsigned long long a,
                                      unsigned long long b) {
    asm("fma.rn.f32x2 %0, %1, %2, %0;" : "+l"(d) : "l"(a), "l"(b));
}
__device__ __forceinline__ float tanh_fast(float x) {
    float y;
    asm("tanh.approx.f32 %0, %1;" : "=f"(y) : "f"(x));
    return y;
}

// Shared pool (floats).
// SS path:  As/Bs = 2*32*132 = 8448.
// MLP path: As(32*68)+Bs(32*68)+Xs(64*36)+Wt(32*36)+sw(33) = 7841.
#define POOL_FLOATS 8448

// ---------------------------------------------------------------------------
// Projection pass (MLP tiles): dst[d][row] = 0.5*(X[row,:]@W[:,d]+b1d)
// dst k-major [32][68]. L1-lean: X read as BROADCAST float4 (1 wf), W held
// transposed Wt[d][f] so each lane reads its own float4 (4 wf / 4 f-values).
// ---------------------------------------------------------------------------
__device__ __forceinline__ void proj_pass(const float* __restrict__ src,
                                          const float* __restrict__ w,
                                          const float* __restrict__ b1,
                                          float* Xs, float* Wt, float* dst,
                                          int tid) {
    for (int l = tid; l < 512; l += 256) {
        const int row = l >> 3;
        const int c = (l & 7) << 2;
        const float4 v = *(const float4*)(src + row * 32 + c);
        *(float4*)(Xs + row * 36 + c) = v;
    }
    // w is [f][d] (f=0..31 rows, d=0..31 cols); store transposed Wt[d][f].
    for (int l = tid; l < 1024; l += 256)
        Wt[(l & 31) * 36 + (l >> 5)] = w[l];
    __syncthreads();

    const int d = tid & 31;
    const int rg = tid >> 5;
    float acc[8];
    const float bv = b1 ? b1[d] : 0.f;
#pragma unroll
    for (int j = 0; j < 8; j++) acc[j] = bv;

    const float* xrow = Xs + rg * 8 * 36;
#pragma unroll
    for (int fq = 0; fq < 8; fq++) {
        const float4 w4 = *(const float4*)(Wt + d * 36 + fq * 4);
#pragma unroll
        for (int j = 0; j < 8; j++) {
            const float4 x4 = *(const float4*)(xrow + j * 36 + fq * 4);
            acc[j] = fmaf(x4.x, w4.x, acc[j]);
            acc[j] = fmaf(x4.y, w4.y, acc[j]);
            acc[j] = fmaf(x4.z, w4.z, acc[j]);
            acc[j] = fmaf(x4.w, w4.w, acc[j]);
        }
    }
#pragma unroll
    for (int j = 0; j < 8; j++) dst[d * 68 + rg * 8 + j] = 0.5f * acc[j];
    __syncthreads();
}

// ---------------------------------------------------------------------------
// Fused kernel. 72 block-slots per batch:
//   r even -> s = r/2 < 36 : SS gram 128x128 triangular tile (ti<=tj),
//             mirror tile written directly (scattered STG, L2 merges).
//   r odd  -> m = r/2 : m<16 ST (64x64), m<32 TS, m==32 TT gram, else idle.
// ---------------------------------------------------------------------------
__global__ __launch_bounds__(256, 2) void adj_fused_kernel(
    const float* __restrict__ spatial, const float* __restrict__ temporal,
    const float* __restrict__ st_w1, const float* __restrict__ st_b1,
    const float* __restrict__ st_w2, const float* __restrict__ st_b2,
    const float* __restrict__ ts_w1, const float* __restrict__ ts_b1,
    const float* __restrict__ ts_w2, const float* __restrict__ ts_b2,
    float* __restrict__ out) {
    __shared__ float pool[POOL_FLOATS];

    const int b = blockIdx.x / 72;
    const int r = blockIdx.x % 72;
    const int tid = threadIdx.x;

    if ((r & 1) == 0) {
        // ============ SS gram: triangular 128x128 tile, 8x8 FFMA2 ==========
        const int s = r >> 1;  // 0..35
        int ti = 0, rem = s;
#pragma unroll
        for (int t = 0; t < 8; t++) {
            if (rem >= 8 - ti) { rem -= 8 - ti; ti++; }
        }
        const int tj = ti + rem;

        float* As = pool;               // [32][132] k-major
        float* Bs = pool + 32 * 132;

        const float* Asrc = spatial + ((size_t)b * 1024 + ti * 128) * 32;
        const float* Bsrc = spatial + ((size_t)b * 1024 + tj * 128) * 32;
        for (int l = tid; l < 1024; l += 256) {
            const int row = l >> 3;
            const int kq = (l & 7) << 2;
            const float4 va = *(const float4*)(Asrc + row * 32 + kq);
            As[(kq + 0) * 132 + row] = va.x;
            As[(kq + 1) * 132 + row] = va.y;
            As[(kq + 2) * 132 + row] = va.z;
            As[(kq + 3) * 132 + row] = va.w;
            const float4 vb = *(const float4*)(Bsrc + row * 32 + kq);
            Bs[(kq + 0) * 132 + row] = vb.x;
            Bs[(kq + 1) * 132 + row] = vb.y;
            Bs[(kq + 2) * 132 + row] = vb.z;
            Bs[(kq + 3) * 132 + row] = vb.w;
        }
        __syncthreads();

        const int tx = tid & 15;  // j-quad: cols tx*4.. and 64+tx*4..
        const int ty = tid >> 4;  // i-tile 0..15: rows ty*8..
        unsigned long long acc[8][4];
#pragma unroll
        for (int i = 0; i < 8; i++)
#pragma unroll
            for (int jp = 0; jp < 4; jp++) acc[i][jp] = 0ull;

        const float* Ap = As + ty * 8;
        const float* Bp = Bs + tx * 4;

        // Software-pipelined mainloop; B read as consecutive-lane float4s
        // (cols tx*4 and 64+tx*4) -> 2 wf per LDS.128 instead of 4.
        float4 a0 = *(const float4*)(Ap);
        float4 a1 = *(const float4*)(Ap + 4);
        float4 b0 = *(const float4*)(Bp);
        float4 b1v = *(const float4*)(Bp + 64);
#pragma unroll
        for (int k = 0; k < 32; k++) {
            float4 na0, na1, nb0, nb1;
            if (k < 31) {
                na0 = *(const float4*)(Ap + (k + 1) * 132);
                na1 = *(const float4*)(Ap + (k + 1) * 132 + 4);
                nb0 = *(const float4*)(Bp + (k + 1) * 132);
                nb1 = *(const float4*)(Bp + (k + 1) * 132 + 64);
            }
            unsigned long long bp[4];
            bp[0] = pack2(b0.x, b0.y);
            bp[1] = pack2(b0.z, b0.w);
            bp[2] = pack2(b1v.x, b1v.y);
            bp[3] = pack2(b1v.z, b1v.w);
            const float av[8] = {a0.x, a0.y, a0.z, a0.w,
                                 a1.x, a1.y, a1.z, a1.w};
#pragma unroll
            for (int i = 0; i < 8; i++) {
                const unsigned long long ad = pack2(av[i], av[i]);
#pragma unroll
                for (int jp = 0; jp < 4; jp++) ffma2(acc[i][jp], ad, bp[jp]);
            }
            a0 = na0; a1 = na1; b0 = nb0; b1v = nb1;
        }

        // Activate into v[i][j]: j 0..3 -> cols tx*4+j, j 4..7 -> 64+tx*4+j-4
        float v[8][8];
#pragma unroll
        for (int i = 0; i < 8; i++) {
#pragma unroll
            for (int jp = 0; jp < 4; jp++)
                unpack2(v[i][2 * jp], v[i][2 * jp + 1], acc[i][jp]);
#pragma unroll
            for (int j = 0; j < 8; j++)
                v[i][j] = tanh_fast(fmaxf(v[i][j], 0.f));
        }

        // Normal tile store (coalesced).
        float* ob = out + ((size_t)b * 1088 + ti * 128 + ty * 8) * 1088 +
                    tj * 128 + tx * 4;
#pragma unroll
        for (int i = 0; i < 8; i++) {
            float4 o0 = {v[i][0], v[i][1], v[i][2], v[i][3]};
            float4 o1 = {v[i][4], v[i][5], v[i][6], v[i][7]};
            *(float4*)(ob + (size_t)i * 1088) = o0;
            *(float4*)(ob + (size_t)i * 1088 + 64) = o1;
        }

        if (ti == tj) return;  // diagonal: no mirror

        // Mirror tile (tj,ti): direct transposed stores. Each thread owns 8
        // full columns j -> mirror rows; rows ty*8..ty*8+7 are contiguous in
        // the mirror row -> 2 float4 per column. Scattered across lanes but
        // q-adjacent columns fill L2 sectors.
        float* om =
            out + ((size_t)b * 1088 + tj * 128) * 1088 + ti * 128 + ty * 8;
#pragma unroll
        for (int j = 0; j < 8; j++) {
            const int col = (j < 4) ? tx * 4 + j : 64 + tx * 4 + (j - 4);
            float4 lo = {v[0][j], v[1][j], v[2][j], v[3][j]};
            float4 hi = {v[4][j], v[5][j], v[6][j], v[7][j]};
            *(float4*)(om + (size_t)col * 1088) = lo;
            *(float4*)(om + (size_t)col * 1088 + 4) = hi;
        }
        return;
    }

    // ==================== MLP (ST / TS) and TT gram: 64x64 tiles ===========
    const int m = r >> 1;
    if (m > 32) return;  // idle slots
    float* As = pool;               // [32][68] k-major
    float* Bs = pool + 32 * 68;
    float* Xs = pool + 2 * 32 * 68;                      // [64][36]
    float* Wt = pool + 2 * 32 * 68 + 64 * 36;            // [32][36] transposed
    float* sw = pool + 2 * 32 * 68 + 64 * 36 + 32 * 36;  // [33]

    int gi0, gj0;
    const bool isGram = (m == 32);

    if (isGram) {
        const float* Tsrc = temporal + (size_t)b * 64 * 32;
        for (int l = tid; l < 512; l += 256) {
            const int row = l >> 3;
            const int kq = (l & 7) << 2;
            const float4 v = *(const float4*)(Tsrc + row * 32 + kq);
            As[(kq + 0) * 68 + row] = v.x;
            As[(kq + 1) * 68 + row] = v.y;
            As[(kq + 2) * 68 + row] = v.z;
            As[(kq + 3) * 68 + row] = v.w;
            Bs[(kq + 0) * 68 + row] = v.x;
            Bs[(kq + 1) * 68 + row] = v.y;
            Bs[(kq + 2) * 68 + row] = v.z;
            Bs[(kq + 3) * 68 + row] = v.w;
        }
        __syncthreads();
        gi0 = 1024;
        gj0 = 1024;
    } else {
        const bool isST = (m < 16);
        const float* w1 = isST ? st_w1 : ts_w1;
        const float* b1 = isST ? st_b1 : ts_b1;
        const float* w2 = isST ? st_w2 : ts_w2;
        const float* b2 = isST ? st_b2 : ts_b2;
        const float* asrc;
        const float* bsrc;
        if (isST) {
            asrc = spatial + ((size_t)b * 1024 + m * 64) * 32;
            bsrc = temporal + (size_t)b * 64 * 32;
            gi0 = m * 64;
            gj0 = 1024;
        } else {
            asrc = temporal + (size_t)b * 64 * 32;
            bsrc = spatial + ((size_t)b * 1024 + (m - 16) * 64) * 32;
            gi0 = 1024;
            gj0 = (m - 16) * 64;
        }

        if (tid < 32) sw[tid] = 0.5f * w2[tid];
        proj_pass(asrc, w1, b1, Xs, Wt, As, tid);  // a' (sync covers sw)
        if (tid == 0) {
            float c = b2[0];
#pragma unroll
            for (int k = 0; k < 32; k++) c += sw[k];
            sw[32] = c;
        }
        proj_pass(bsrc, w1 + 1024, nullptr, Xs, Wt, Bs, tid);  // b'
    }

    const int tx = tid & 15;
    const int ty = tid >> 4;
    float acc[4][4];
#pragma unroll
    for (int i = 0; i < 4; i++)
#pragma unroll
        for (int j = 0; j < 4; j++) acc[i][j] = 0.f;

    const float* ap = As + ty * 4;
    const float* bp = Bs + tx * 4;

    if (isGram) {
#pragma unroll
        for (int k = 0; k < 32; k++) {
            const float4 a = *(const float4*)(ap + k * 68);
            const float4 bb = *(const float4*)(bp + k * 68);
            const float av[4] = {a.x, a.y, a.z, a.w};
            const float bv[4] = {bb.x, bb.y, bb.z, bb.w};
#pragma unroll
            for (int i = 0; i < 4; i++)
#pragma unroll
                for (int j = 0; j < 4; j++)
                    acc[i][j] = fmaf(av[i], bv[j], acc[i][j]);
        }
    } else {
#pragma unroll
        for (int k = 0; k < 32; k++) {
            const float4 a = *(const float4*)(ap + k * 68);
            const float4 bb = *(const float4*)(bp + k * 68);
            const float av[4] = {a.x, a.y, a.z, a.w};
            const float bv[4] = {bb.x, bb.y, bb.z, bb.w};
            const float w = sw[k];
#pragma unroll
            for (int i = 0; i < 4; i++)
#pragma unroll
                for (int j = 0; j < 4; j++) {
                    const float t = tanh_fast(av[i] + bv[j]);
                    acc[i][j] = fmaf(t, w, acc[i][j]);
                }
        }
        const float c0 = sw[32];
#pragma unroll
        for (int i = 0; i < 4; i++)
#pragma unroll
            for (int j = 0; j < 4; j++) acc[i][j] += c0;
    }

    float* ob = out + ((size_t)b * 1088 + gi0 + ty * 4) * 1088 + gj0 + tx * 4;
#pragma unroll
    for (int i = 0; i < 4; i++) {
        float4 v;
        v.x = tanh_fast(fmaxf(acc[i][0], 0.f));
        v.y = tanh_fast(fmaxf(acc[i][1], 0.f));
        v.z = tanh_fast(fmaxf(acc[i][2], 0.f));
        v.w = tanh_fast(fmaxf(acc[i][3], 0.f));
        *(float4*)(ob + (size_t)i * 1088) = v;
    }
}

extern "C" void kernel_launch(void* const* d_in, const int* in_sizes, int n_in,
                              void* d_out, int out_size) {
    const float* spatial = (const float*)d_in[0];   // [32,1024,32]
    const float* temporal = (const float*)d_in[1];  // [32,64,32]
    const float* st_w1 = (const float*)d_in[2];     // [64,32]
    const float* st_b1 = (const float*)d_in[3];     // [32]
    const float* st_w2 = (const float*)d_in[4];     // [32,1]
    const float* st_b2 = (const float*)d_in[5];     // [1]
    const float* ts_w1 = (const float*)d_in[6];
    const float* ts_b1 = (const float*)d_in[7];
    const float* ts_w2 = (const float*)d_in[8];
    const float* ts_b2 = (const float*)d_in[9];
    float* out = (float*)d_out;                     // [32,1088,1088]

    adj_fused_kernel<<<32 * 72, 256>>>(spatial, temporal, st_w1, st_b1, st_w2,
                                       st_b2, ts_w1, ts_b1, ts_w2, ts_b2, out);
}

// round 8
// speedup vs baseline: 1.3675x; 1.0416x over previous
#include <cuda_runtime.h>
#include <cstdint>

// ---------------------------------------------------------------------------
// f32x2 packed helpers (FFMA2 only reachable via PTX fma.rn.f32x2)
// ---------------------------------------------------------------------------
__device__ __forceinline__ unsigned long long pack2(float lo, float hi) {
    unsigned long long r;
    asm("mov.b64 %0, {%1, %2};" : "=l"(r) : "f"(lo), "f"(hi));
    return r;
}
__device__ __forceinline__ void unpack2(float& lo, float& hi,
                                        unsigned long long v) {
    asm("mov.b64 {%0, %1}, %2;" : "=f"(lo), "=f"(hi) : "l"(v));
}
__device__ __forceinline__ void ffma2(unsigned long long& d,
                                      unsigned long long a,
                                      unsigned long long b) {
    asm("fma.rn.f32x2 %0, %1, %2, %0;" : "+l"(d) : "l"(a), "l"(b));
}
__device__ __forceinline__ float tanh_fast(float x) {
    float y;
    asm("tanh.approx.f32 %0, %1;" : "=f"(y) : "f"(x));
    return y;
}

// Shared pool (floats).
// SS path:  As/Bs = 2*32*132 = 8448.
// MLP path: As(32*68)+Bs(32*68)+Xs(64*36)+Wt(32*36)+sw(33) = 7841.
#define POOL_FLOATS 8448

// ---------------------------------------------------------------------------
// Projection pass (512 threads): dst[d][row] = 0.5*(X[row,:]@W[:,d]+b1d)
// dst k-major [32][68]. X via per-lane float4, W transposed Wt[d][f].
// Each (rg,d) thread computes 4 rows.
// ---------------------------------------------------------------------------
__device__ __forceinline__ void proj_pass(const float* __restrict__ src,
                                          const float* __restrict__ w,
                                          const float* __restrict__ b1,
                                          float* Xs, float* Wt, float* dst,
                                          int tid) {
    {
        const int row = tid >> 3;
        const int c = (tid & 7) << 2;
        *(float4*)(Xs + row * 36 + c) = *(const float4*)(src + row * 32 + c);
    }
    for (int l = tid; l < 1024; l += 512)
        Wt[(l & 31) * 36 + (l >> 5)] = w[l];
    __syncthreads();

    const int d = tid & 31;
    const int rg = tid >> 5;  // 0..15 -> rows rg*4..rg*4+3
    const float bv = b1 ? b1[d] : 0.f;
    float acc[4] = {bv, bv, bv, bv};

    const float* xrow = Xs + rg * 4 * 36;
#pragma unroll
    for (int fq = 0; fq < 8; fq++) {
        const float4 w4 = *(const float4*)(Wt + d * 36 + fq * 4);
#pragma unroll
        for (int j = 0; j < 4; j++) {
            const float4 x4 = *(const float4*)(xrow + j * 36 + fq * 4);
            acc[j] = fmaf(x4.x, w4.x, acc[j]);
            acc[j] = fmaf(x4.y, w4.y, acc[j]);
            acc[j] = fmaf(x4.z, w4.z, acc[j]);
            acc[j] = fmaf(x4.w, w4.w, acc[j]);
        }
    }
#pragma unroll
    for (int j = 0; j < 4; j++) dst[d * 68 + rg * 4 + j] = 0.5f * acc[j];
    __syncthreads();
}

// ---------------------------------------------------------------------------
// Fused kernel, 512 threads. 72 block-slots per batch:
//   r even -> s = r/2 < 36 : SS gram 128x128 triangular tile (ti<=tj),
//             mirror tile written directly.
//   r odd  -> m = r/2 : m<16 ST (64x64), m<32 TS, m==32 TT gram, else idle.
// ---------------------------------------------------------------------------
__global__ __launch_bounds__(512, 2) void adj_fused_kernel(
    const float* __restrict__ spatial, const float* __restrict__ temporal,
    const float* __restrict__ st_w1, const float* __restrict__ st_b1,
    const float* __restrict__ st_w2, const float* __restrict__ st_b2,
    const float* __restrict__ ts_w1, const float* __restrict__ ts_b1,
    const float* __restrict__ ts_w2, const float* __restrict__ ts_b2,
    float* __restrict__ out) {
    __shared__ float pool[POOL_FLOATS];

    const int b = blockIdx.x / 72;
    const int r = blockIdx.x % 72;
    const int tid = threadIdx.x;

    if ((r & 1) == 0) {
        // ====== SS gram: triangular 128x128 tile, 4x8 per thread, FFMA2 ====
        const int s = r >> 1;  // 0..35
        int ti = 0, rem = s;
#pragma unroll
        for (int t = 0; t < 8; t++) {
            if (rem >= 8 - ti) { rem -= 8 - ti; ti++; }
        }
        const int tj = ti + rem;

        float* As = pool;               // [32][132] k-major
        float* Bs = pool + 32 * 132;

        const float* Asrc = spatial + ((size_t)b * 1024 + ti * 128) * 32;
        const float* Bsrc = spatial + ((size_t)b * 1024 + tj * 128) * 32;
        for (int l = tid; l < 1024; l += 512) {
            const int row = l >> 3;
            const int kq = (l & 7) << 2;
            const float4 va = *(const float4*)(Asrc + row * 32 + kq);
            As[(kq + 0) * 132 + row] = va.x;
            As[(kq + 1) * 132 + row] = va.y;
            As[(kq + 2) * 132 + row] = va.z;
            As[(kq + 3) * 132 + row] = va.w;
            const float4 vb = *(const float4*)(Bsrc + row * 32 + kq);
            Bs[(kq + 0) * 132 + row] = vb.x;
            Bs[(kq + 1) * 132 + row] = vb.y;
            Bs[(kq + 2) * 132 + row] = vb.z;
            Bs[(kq + 3) * 132 + row] = vb.w;
        }
        __syncthreads();

        const int tx = tid & 15;  // cols tx*4.. and 64+tx*4..
        const int ty = tid >> 4;  // 0..31 -> rows ty*4..
        unsigned long long acc[4][4];
#pragma unroll
        for (int i = 0; i < 4; i++)
#pragma unroll
            for (int jp = 0; jp < 4; jp++) acc[i][jp] = 0ull;

        const float* Ap = As + ty * 4;
        // B read directly as packed u64 pairs (even float offsets -> aligned)
        const unsigned long long* Bq =
            (const unsigned long long*)(Bs + tx * 4);
#pragma unroll
        for (int k = 0; k < 32; k++) {
            const float4 a = *(const float4*)(Ap + k * 132);
            const unsigned long long bp0 = Bq[k * 66];
            const unsigned long long bp1 = Bq[k * 66 + 1];
            const unsigned long long bp2 = Bq[k * 66 + 32];
            const unsigned long long bp3 = Bq[k * 66 + 33];
            const float av[4] = {a.x, a.y, a.z, a.w};
#pragma unroll
            for (int i = 0; i < 4; i++) {
                const unsigned long long ad = pack2(av[i], av[i]);
                ffma2(acc[i][0], ad, bp0);
                ffma2(acc[i][1], ad, bp1);
                ffma2(acc[i][2], ad, bp2);
                ffma2(acc[i][3], ad, bp3);
            }
        }

        // Activate: v[i][j], j 0..3 -> cols tx*4+j, j 4..7 -> 64+tx*4+(j-4).
        float v[4][8];
#pragma unroll
        for (int i = 0; i < 4; i++) {
#pragma unroll
            for (int jp = 0; jp < 4; jp++)
                unpack2(v[i][2 * jp], v[i][2 * jp + 1], acc[i][jp]);
#pragma unroll
            for (int j = 0; j < 8; j++)
                v[i][j] = tanh_fast(fmaxf(v[i][j], 0.f));
        }

        // Normal tile store (coalesced).
        float* ob = out + ((size_t)b * 1088 + ti * 128 + ty * 4) * 1088 +
                    tj * 128 + tx * 4;
#pragma unroll
        for (int i = 0; i < 4; i++) {
            float4 o0 = {v[i][0], v[i][1], v[i][2], v[i][3]};
            float4 o1 = {v[i][4], v[i][5], v[i][6], v[i][7]};
            *(float4*)(ob + (size_t)i * 1088) = o0;
            *(float4*)(ob + (size_t)i * 1088 + 64) = o1;
        }

        if (ti == tj) return;  // diagonal: no mirror

        // Mirror tile (tj,ti): direct transposed stores; each thread owns 8
        // columns, rows ty*4..ty*4+3 contiguous -> one float4 per column.
        float* om =
            out + ((size_t)b * 1088 + tj * 128) * 1088 + ti * 128 + ty * 4;
#pragma unroll
        for (int j = 0; j < 8; j++) {
            const int col = (j < 4) ? tx * 4 + j : 64 + tx * 4 + (j - 4);
            float4 mv = {v[0][j], v[1][j], v[2][j], v[3][j]};
            *(float4*)(om + (size_t)col * 1088) = mv;
        }
        return;
    }

    // ==================== MLP (ST / TS) and TT gram: 64x64 tiles ===========
    const int m = r >> 1;
    if (m > 32) return;  // idle slots
    float* As = pool;               // [32][68] k-major
    float* Bs = pool + 32 * 68;
    float* Xs = pool + 2 * 32 * 68;                      // [64][36]
    float* Wt = pool + 2 * 32 * 68 + 64 * 36;            // [32][36] transposed
    float* sw = pool + 2 * 32 * 68 + 64 * 36 + 32 * 36;  // [33]

    int gi0, gj0;
    const bool isGram = (m == 32);

    if (isGram) {
        const float* Tsrc = temporal + (size_t)b * 64 * 32;
        {
            const int row = tid >> 3;
            const int kq = (tid & 7) << 2;
            const float4 v = *(const float4*)(Tsrc + row * 32 + kq);
            As[(kq + 0) * 68 + row] = v.x;
            As[(kq + 1) * 68 + row] = v.y;
            As[(kq + 2) * 68 + row] = v.z;
            As[(kq + 3) * 68 + row] = v.w;
            Bs[(kq + 0) * 68 + row] = v.x;
            Bs[(kq + 1) * 68 + row] = v.y;
            Bs[(kq + 2) * 68 + row] = v.z;
            Bs[(kq + 3) * 68 + row] = v.w;
        }
        __syncthreads();
        gi0 = 1024;
        gj0 = 1024;
    } else {
        const bool isST = (m < 16);
        const float* w1 = isST ? st_w1 : ts_w1;
        const float* b1 = isST ? st_b1 : ts_b1;
        const float* w2 = isST ? st_w2 : ts_w2;
        const float* b2 = isST ? st_b2 : ts_b2;
        const float* asrc;
        const float* bsrc;
        if (isST) {
            asrc = spatial + ((size_t)b * 1024 + m * 64) * 32;
            bsrc = temporal + (size_t)b * 64 * 32;
            gi0 = m * 64;
            gj0 = 1024;
        } else {
            asrc = temporal + (size_t)b * 64 * 32;
            bsrc = spatial + ((size_t)b * 1024 + (m - 16) * 64) * 32;
            gi0 = 1024;
            gj0 = (m - 16) * 64;
        }

        if (tid < 32) sw[tid] = 0.5f * w2[tid];
        proj_pass(asrc, w1, b1, Xs, Wt, As, tid);  // a' (sync covers sw)
        if (tid == 0) {
            float c = b2[0];
#pragma unroll
            for (int k = 0; k < 32; k++) c += sw[k];
            sw[32] = c;
        }
        proj_pass(bsrc, w1 + 1024, nullptr, Xs, Wt, Bs, tid);  // b'
    }

    const int tx = tid & 15;  // cols tx*4
    const int ty = tid >> 4;  // 0..31 -> rows ty*2
    float acc[2][4];
#pragma unroll
    for (int i = 0; i < 2; i++)
#pragma unroll
        for (int j = 0; j < 4; j++) acc[i][j] = 0.f;

    const float* ap = As + ty * 2;
    const float* bp = Bs + tx * 4;

    if (isGram) {
#pragma unroll
        for (int k = 0; k < 32; k++) {
            const float2 a = *(const float2*)(ap + k * 68);
            const float4 bb = *(const float4*)(bp + k * 68);
            const float av[2] = {a.x, a.y};
            const float bv[4] = {bb.x, bb.y, bb.z, bb.w};
#pragma unroll
            for (int i = 0; i < 2; i++)
#pragma unroll
                for (int j = 0; j < 4; j++)
                    acc[i][j] = fmaf(av[i], bv[j], acc[i][j]);
        }
    } else {
#pragma unroll
        for (int k = 0; k < 32; k++) {
            const float2 a = *(const float2*)(ap + k * 68);
            const float4 bb = *(const float4*)(bp + k * 68);
            const float av[2] = {a.x, a.y};
            const float bv[4] = {bb.x, bb.y, bb.z, bb.w};
            const float w = sw[k];
#pragma unroll
            for (int i = 0; i < 2; i++)
#pragma unroll
                for (int j = 0; j < 4; j++) {
                    const float t = tanh_fast(av[i] + bv[j]);
                    acc[i][j] = fmaf(t, w, acc[i][j]);
                }
        }
        const float c0 = sw[32];
#pragma unroll
        for (int i = 0; i < 2; i++)
#pragma unroll
            for (int j = 0; j < 4; j++) acc[i][j] += c0;
    }

    float* ob = out + ((size_t)b * 1088 + gi0 + ty * 2) * 1088 + gj0 + tx * 4;
#pragma unroll
    for (int i = 0; i < 2; i++) {
        float4 v;
        v.x = tanh_fast(fmaxf(acc[i][0], 0.f));
        v.y = tanh_fast(fmaxf(acc[i][1], 0.f));
        v.z = tanh_fast(fmaxf(acc[i][2], 0.f));
        v.w = tanh_fast(fmaxf(acc[i][3], 0.f));
        *(float4*)(ob + (size_t)i * 1088) = v;
    }
}

extern "C" void kernel_launch(void* const* d_in, const int* in_sizes, int n_in,
                              void* d_out, int out_size) {
    const float* spatial = (const float*)d_in[0];   // [32,1024,32]
    const float* temporal = (const float*)d_in[1];  // [32,64,32]
    const float* st_w1 = (const float*)d_in[2];     // [64,32]
    const float* st_b1 = (const float*)d_in[3];     // [32]
    const float* st_w2 = (const float*)d_in[4];     // [32,1]
    const float* st_b2 = (const float*)d_in[5];     // [1]
    const float* ts_w1 = (const float*)d_in[6];
    const float* ts_b1 = (const float*)d_in[7];
    const float* ts_w2 = (const float*)d_in[8];
    const float* ts_b2 = (const float*)d_in[9];
    float* out = (float*)d_out;                     // [32,1088,1088]

    adj_fused_kernel<<<32 * 72, 512>>>(spatial, temporal, st_w1, st_b1, st_w2,
                                       st_b2, ts_w1, ts_b1, ts_w2, ts_b2, out);
}

// round 9
// speedup vs baseline: 1.4402x; 1.0532x over previous
#include <cuda_runtime.h>
#include <cstdint>

// ---------------------------------------------------------------------------
// f32x2 packed helpers (FFMA2 only reachable via PTX fma.rn.f32x2)
// ---------------------------------------------------------------------------
__device__ __forceinline__ unsigned long long pack2(float lo, float hi) {
    unsigned long long r;
    asm("mov.b64 %0, {%1, %2};" : "=l"(r) : "f"(lo), "f"(hi));
    return r;
}
__device__ __forceinline__ void unpack2(float& lo, float& hi,
                                        unsigned long long v) {
    asm("mov.b64 {%0, %1}, %2;" : "=f"(lo), "=f"(hi) : "l"(v));
}
__device__ __forceinline__ void ffma2(unsigned long long& d,
                                      unsigned long long a,
                                      unsigned long long b) {
    asm("fma.rn.f32x2 %0, %1, %2, %0;" : "+l"(d) : "l"(a), "l"(b));
}
__device__ __forceinline__ float tanh_fast(float x) {
    float y;
    asm("tanh.approx.f32 %0, %1;" : "=f"(y) : "f"(x));
    return y;
}

// Shared pool (floats).
// SS path:  As(32*132) + Bs(32*68) = 6400.
// MLP path: As(32*68)+Bs(32*68)+Xs(64*36)+Wt(32*36)+sw(33) = 7841.
#define POOL_FLOATS 7841

// ---------------------------------------------------------------------------
// Projection pass (256 threads): dst[d][row] = 0.5*(X[row,:]@W[:,d]+b1d)
// dst k-major [32][68]. X per-lane float4, W transposed Wt[d][f].
// Each (rg,d) thread computes 8 rows.
// ---------------------------------------------------------------------------
__device__ __forceinline__ void proj_pass(const float* __restrict__ src,
                                          const float* __restrict__ w,
                                          const float* __restrict__ b1,
                                          float* Xs, float* Wt, float* dst,
                                          int tid) {
    for (int l = tid; l < 512; l += 256) {
        const int row = l >> 3;
        const int c = (l & 7) << 2;
        *(float4*)(Xs + row * 36 + c) = *(const float4*)(src + row * 32 + c);
    }
    for (int l = tid; l < 1024; l += 256)
        Wt[(l & 31) * 36 + (l >> 5)] = w[l];
    __syncthreads();

    const int d = tid & 31;
    const int rg = tid >> 5;  // 0..7 -> rows rg*8..rg*8+7
    const float bv = b1 ? b1[d] : 0.f;
    float acc[8];
#pragma unroll
    for (int j = 0; j < 8; j++) acc[j] = bv;

    const float* xrow = Xs + rg * 8 * 36;
#pragma unroll
    for (int fq = 0; fq < 8; fq++) {
        const float4 w4 = *(const float4*)(Wt + d * 36 + fq * 4);
#pragma unroll
        for (int j = 0; j < 8; j++) {
            const float4 x4 = *(const float4*)(xrow + j * 36 + fq * 4);
            acc[j] = fmaf(x4.x, w4.x, acc[j]);
            acc[j] = fmaf(x4.y, w4.y, acc[j]);
            acc[j] = fmaf(x4.z, w4.z, acc[j]);
            acc[j] = fmaf(x4.w, w4.w, acc[j]);
        }
    }
#pragma unroll
    for (int j = 0; j < 8; j++) dst[d * 68 + rg * 8 + j] = 0.5f * acc[j];
    __syncthreads();
}

// ---------------------------------------------------------------------------
// Fused kernel, 256 threads, 4 CTAs/SM. 108 block-slots per batch:
//   r%3==0/1 -> SS half-tile: s=r/3 (triangular ti<=tj), h=r%3 selects the
//               64-col half of the 128x128 tile. Mirror stored directly.
//   r%3==2   -> m=r/3: m<16 ST (64x64), m<32 TS, m==32 TT gram, else idle.
// SS and MLP half-blocks have similar duration -> good per-SM pipe mixing.
// ---------------------------------------------------------------------------
__global__ __launch_bounds__(256, 4) void adj_fused_kernel(
    const float* __restrict__ spatial, const float* __restrict__ temporal,
    const float* __restrict__ st_w1, const float* __restrict__ st_b1,
    const float* __restrict__ st_w2, const float* __restrict__ st_b2,
    const float* __restrict__ ts_w1, const float* __restrict__ ts_b1,
    const float* __restrict__ ts_w2, const float* __restrict__ ts_b2,
    float* __restrict__ out) {
    __shared__ float pool[POOL_FLOATS];

    const int b = blockIdx.x / 108;
    const int r = blockIdx.x % 108;
    const int tid = threadIdx.x;
    const int rm = r % 3;

    if (rm != 2) {
        // ====== SS gram: 128x64 half-tile, 8x4 per thread, FFMA2 ===========
        const int s = r / 3;  // 0..35 triangular index
        int ti = 0, rem = s;
#pragma unroll
        for (int t = 0; t < 8; t++) {
            if (rem >= 8 - ti) { rem -= 8 - ti; ti++; }
        }
        const int tj = ti + rem;
        const int cj = tj * 128 + rm * 64;  // global col base (64 cols)

        float* As = pool;               // [32][132] k-major, 128 rows
        float* Bs = pool + 32 * 132;    // [32][68]  k-major, 64 cols

        const float* Asrc = spatial + ((size_t)b * 1024 + ti * 128) * 32;
        const float* Bsrc = spatial + ((size_t)b * 1024 + cj) * 32;
        for (int l = tid; l < 1024; l += 256) {
            const int row = l >> 3;
            const int kq = (l & 7) << 2;
            const float4 va = *(const float4*)(Asrc + row * 32 + kq);
            As[(kq + 0) * 132 + row] = va.x;
            As[(kq + 1) * 132 + row] = va.y;
            As[(kq + 2) * 132 + row] = va.z;
            As[(kq + 3) * 132 + row] = va.w;
        }
        for (int l = tid; l < 512; l += 256) {
            const int row = l >> 3;
            const int kq = (l & 7) << 2;
            const float4 vb = *(const float4*)(Bsrc + row * 32 + kq);
            Bs[(kq + 0) * 68 + row] = vb.x;
            Bs[(kq + 1) * 68 + row] = vb.y;
            Bs[(kq + 2) * 68 + row] = vb.z;
            Bs[(kq + 3) * 68 + row] = vb.w;
        }
        __syncthreads();

        const int tx = tid & 15;  // cols tx*4..tx*4+3
        const int ty = tid >> 4;  // rows ty*8..ty*8+7
        unsigned long long acc[8][2];
#pragma unroll
        for (int i = 0; i < 8; i++) {
            acc[i][0] = 0ull;
            acc[i][1] = 0ull;
        }

        const float* Ap = As + ty * 8;
        const unsigned long long* Bq = (const unsigned long long*)(Bs + tx * 4);
#pragma unroll
        for (int k = 0; k < 32; k++) {
            const float4 a0 = *(const float4*)(Ap + k * 132);
            const float4 a1 = *(const float4*)(Ap + k * 132 + 4);
            const unsigned long long bp0 = Bq[k * 34];
            const unsigned long long bp1 = Bq[k * 34 + 1];
            const float av[8] = {a0.x, a0.y, a0.z, a0.w,
                                 a1.x, a1.y, a1.z, a1.w};
#pragma unroll
            for (int i = 0; i < 8; i++) {
                const unsigned long long ad = pack2(av[i], av[i]);
                ffma2(acc[i][0], ad, bp0);
                ffma2(acc[i][1], ad, bp1);
            }
        }

        // Activate.
        float v[8][4];
#pragma unroll
        for (int i = 0; i < 8; i++) {
            unpack2(v[i][0], v[i][1], acc[i][0]);
            unpack2(v[i][2], v[i][3], acc[i][1]);
#pragma unroll
            for (int j = 0; j < 4; j++)
                v[i][j] = tanh_fast(fmaxf(v[i][j], 0.f));
        }

        // Normal store: rows ti*128+ty*8.., cols cj+tx*4.
        float* ob =
            out + ((size_t)b * 1088 + ti * 128 + ty * 8) * 1088 + cj + tx * 4;
#pragma unroll
        for (int i = 0; i < 8; i++) {
            float4 o = {v[i][0], v[i][1], v[i][2], v[i][3]};
            *(float4*)(ob + (size_t)i * 1088) = o;
        }

        if (ti == tj) return;  // diagonal tile: both halves computed, no mirror

        // Mirror: rows cj+col, cols ti*128+ty*8.. (two float4 per column).
        float* om =
            out + ((size_t)b * 1088 + cj) * 1088 + ti * 128 + ty * 8;
#pragma unroll
        for (int j = 0; j < 4; j++) {
            const int col = tx * 4 + j;
            float4 lo = {v[0][j], v[1][j], v[2][j], v[3][j]};
            float4 hi = {v[4][j], v[5][j], v[6][j], v[7][j]};
            *(float4*)(om + (size_t)col * 1088) = lo;
            *(float4*)(om + (size_t)col * 1088 + 4) = hi;
        }
        return;
    }

    // ==================== MLP (ST / TS) and TT gram: 64x64 tiles ===========
    const int m = r / 3;
    if (m > 32) return;  // idle slots
    float* As = pool;               // [32][68] k-major
    float* Bs = pool + 32 * 68;
    float* Xs = pool + 2 * 32 * 68;                      // [64][36]
    float* Wt = pool + 2 * 32 * 68 + 64 * 36;            // [32][36] transposed
    float* sw = pool + 2 * 32 * 68 + 64 * 36 + 32 * 36;  // [33]

    int gi0, gj0;
    const bool isGram = (m == 32);

    if (isGram) {
        const float* Tsrc = temporal + (size_t)b * 64 * 32;
        for (int l = tid; l < 512; l += 256) {
            const int row = l >> 3;
            const int kq = (l & 7) << 2;
            const float4 v = *(const float4*)(Tsrc + row * 32 + kq);
            As[(kq + 0) * 68 + row] = v.x;
            As[(kq + 1) * 68 + row] = v.y;
            As[(kq + 2) * 68 + row] = v.z;
            As[(kq + 3) * 68 + row] = v.w;
            Bs[(kq + 0) * 68 + row] = v.x;
            Bs[(kq + 1) * 68 + row] = v.y;
            Bs[(kq + 2) * 68 + row] = v.z;
            Bs[(kq + 3) * 68 + row] = v.w;
        }
        __syncthreads();
        gi0 = 1024;
        gj0 = 1024;
    } else {
        const bool isST = (m < 16);
        const float* w1 = isST ? st_w1 : ts_w1;
        const float* b1 = isST ? st_b1 : ts_b1;
        const float* w2 = isST ? st_w2 : ts_w2;
        const float* b2 = isST ? st_b2 : ts_b2;
        const float* asrc;
        const float* bsrc;
        if (isST) {
            asrc = spatial + ((size_t)b * 1024 + m * 64) * 32;
            bsrc = temporal + (size_t)b * 64 * 32;
            gi0 = m * 64;
            gj0 = 1024;
        } else {
            asrc = temporal + (size_t)b * 64 * 32;
            bsrc = spatial + ((size_t)b * 1024 + (m - 16) * 64) * 32;
            gi0 = 1024;
            gj0 = (m - 16) * 64;
        }

        if (tid < 32) sw[tid] = 0.5f * w2[tid];
        proj_pass(asrc, w1, b1, Xs, Wt, As, tid);  // a' (sync covers sw)
        if (tid == 0) {
            float c = b2[0];
#pragma unroll
            for (int k = 0; k < 32; k++) c += sw[k];
            sw[32] = c;
        }
        proj_pass(bsrc, w1 + 1024, nullptr, Xs, Wt, Bs, tid);  // b'
    }

    const int tx = tid & 15;  // cols tx*4
    const int ty = tid >> 4;  // rows ty*4
    float acc[4][4];
#pragma unroll
    for (int i = 0; i < 4; i++)
#pragma unroll
        for (int j = 0; j < 4; j++) acc[i][j] = 0.f;

    const float* ap = As + ty * 4;
    const float* bp = Bs + tx * 4;

    if (isGram) {
#pragma unroll
        for (int k = 0; k < 32; k++) {
            const float4 a = *(const float4*)(ap + k * 68);
            const float4 bb = *(const float4*)(bp + k * 68);
            const float av[4] = {a.x, a.y, a.z, a.w};
            const float bv[4] = {bb.x, bb.y, bb.z, bb.w};
#pragma unroll
            for (int i = 0; i < 4; i++)
#pragma unroll
                for (int j = 0; j < 4; j++)
                    acc[i][j] = fmaf(av[i], bv[j], acc[i][j]);
        }
    } else {
#pragma unroll
        for (int k = 0; k < 32; k++) {
            const float4 a = *(const float4*)(ap + k * 68);
            const float4 bb = *(const float4*)(bp + k * 68);
            const float av[4] = {a.x, a.y, a.z, a.w};
            const float bv[4] = {bb.x, bb.y, bb.z, bb.w};
            const float w = sw[k];
#pragma unroll
            for (int i = 0; i < 4; i++)
#pragma unroll
                for (int j = 0; j < 4; j++) {
                    const float t = tanh_fast(av[i] + bv[j]);
                    acc[i][j] = fmaf(t, w, acc[i][j]);
                }
        }
        const float c0 = sw[32];
#pragma unroll
        for (int i = 0; i < 4; i++)
#pragma unroll
            for (int j = 0; j < 4; j++) acc[i][j] += c0;
    }

    float* ob = out + ((size_t)b * 1088 + gi0 + ty * 4) * 1088 + gj0 + tx * 4;
#pragma unroll
    for (int i = 0; i < 4; i++) {
        float4 v;
        v.x = tanh_fast(fmaxf(acc[i][0], 0.f));
        v.y = tanh_fast(fmaxf(acc[i][1], 0.f));
        v.z = tanh_fast(fmaxf(acc[i][2], 0.f));
        v.w = tanh_fast(fmaxf(acc[i][3], 0.f));
        *(float4*)(ob + (size_t)i * 1088) = v;
    }
}

extern "C" void kernel_launch(void* const* d_in, const int* in_sizes, int n_in,
                              void* d_out, int out_size) {
    const float* spatial = (const float*)d_in[0];   // [32,1024,32]
    const float* temporal = (const float*)d_in[1];  // [32,64,32]
    const float* st_w1 = (const float*)d_in[2];     // [64,32]
    const float* st_b1 = (const float*)d_in[3];     // [32]
    const float* st_w2 = (const float*)d_in[4];     // [32,1]
    const float* st_b2 = (const float*)d_in[5];     // [1]
    const float* ts_w1 = (const float*)d_in[6];
    const float* ts_b1 = (const float*)d_in[7];
    const float* ts_w2 = (const float*)d_in[8];
    const float* ts_b2 = (const float*)d_in[9];
    float* out = (float*)d_out;                     // [32,1088,1088]

    adj_fused_kernel<<<32 * 108, 256>>>(spatial, temporal, st_w1, st_b1, st_w2,
                                        st_b2, ts_w1, ts_b1, ts_w2, ts_b2, out);
}

// round 10
// speedup vs baseline: 1.4408x; 1.0004x over previous
#include <cuda_runtime.h>
#include <cuda_fp16.h>
#include <cstdint>

// ---------------------------------------------------------------------------
// packed helpers
// ---------------------------------------------------------------------------
__device__ __forceinline__ unsigned long long pack2(float lo, float hi) {
    unsigned long long r;
    asm("mov.b64 %0, {%1, %2};" : "=l"(r) : "f"(lo), "f"(hi));
    return r;
}
__device__ __forceinline__ void unpack2(float& lo, float& hi,
                                        unsigned long long v) {
    asm("mov.b64 {%0, %1}, %2;" : "=f"(lo), "=f"(hi) : "l"(v));
}
__device__ __forceinline__ void ffma2(unsigned long long& d,
                                      unsigned long long a,
                                      unsigned long long b) {
    asm("fma.rn.f32x2 %0, %1, %2, %0;" : "+l"(d) : "l"(a), "l"(b));
}
__device__ __forceinline__ float tanh_fast(float x) {
    float y;
    asm("tanh.approx.f32 %0, %1;" : "=f"(y) : "f"(x));
    return y;
}
__device__ __forceinline__ unsigned tanh2_fast(unsigned x) {
    unsigned y;
    asm("tanh.approx.f16x2 %0, %1;" : "=r"(y) : "r"(x));
    return y;
}
__device__ __forceinline__ unsigned h22u(__half2 h) {
    return *reinterpret_cast<unsigned*>(&h);
}
__device__ __forceinline__ __half2 u2h2(unsigned u) {
    __half2 h;
    *reinterpret_cast<unsigned*>(&h) = u;
    return h;
}

// Shared pool (floats).
// SS path:  As(32*132)+Bs(32*68) = 6400.
// MLP path: ah2(32*68)+bh2(32*36)+Xs(64*36)+Wt(32*36)+swh(32)+c0 = 6817.
// TT path:  As(32*68)+Bs(32*68) = 4352.
#define POOL_FLOATS 8448

// ---------------------------------------------------------------------------
// Projection pass (256 threads): val[row,d] = 0.5*(X[row,:]@W[:,d]+b1d),
// written as f16x2 for the h2 mainloop. mode 0 (a-side): dst[d][row] =
// half2(v,v), stride 68. mode 1 (b-side): dst[d][rowpair] = half2(v0,v1),
// stride 36.
// ---------------------------------------------------------------------------
__device__ __forceinline__ void proj_pass_h2(const float* __restrict__ src,
                                             const float* __restrict__ w,
                                             const float* __restrict__ b1,
                                             float* Xs, float* Wt,
                                             __half2* dst, int mode, int tid) {
    for (int l = tid; l < 512; l += 256) {
        const int row = l >> 3;
        const int c = (l & 7) << 2;
        *(float4*)(Xs + row * 36 + c) = *(const float4*)(src + row * 32 + c);
    }
    for (int l = tid; l < 1024; l += 256)
        Wt[(l & 31) * 36 + (l >> 5)] = w[l];
    __syncthreads();

    const int d = tid & 31;   // output dim == k index
    const int rg = tid >> 5;  // 0..7 -> rows rg*8..rg*8+7
    const float bv = b1 ? b1[d] : 0.f;
    float acc[8];
#pragma unroll
    for (int j = 0; j < 8; j++) acc[j] = bv;

    const float* xrow = Xs + rg * 8 * 36;
#pragma unroll
    for (int fq = 0; fq < 8; fq++) {
        const float4 w4 = *(const float4*)(Wt + d * 36 + fq * 4);
#pragma unroll
        for (int j = 0; j < 8; j++) {
            const float4 x4 = *(const float4*)(xrow + j * 36 + fq * 4);
            acc[j] = fmaf(x4.x, w4.x, acc[j]);
            acc[j] = fmaf(x4.y, w4.y, acc[j]);
            acc[j] = fmaf(x4.z, w4.z, acc[j]);
            acc[j] = fmaf(x4.w, w4.w, acc[j]);
        }
    }
    if (mode == 0) {
#pragma unroll
        for (int j = 0; j < 8; j++)
            dst[d * 68 + rg * 8 + j] = __float2half2_rn(0.5f * acc[j]);
    } else {
#pragma unroll
        for (int m = 0; m < 4; m++)
            dst[d * 36 + rg * 4 + m] =
                __floats2half2_rn(0.5f * acc[2 * m], 0.5f * acc[2 * m + 1]);
    }
    __syncthreads();
}

// ---------------------------------------------------------------------------
// Fused kernel, 256 threads, 4 CTAs/SM. 108 block-slots per batch:
//   r%3==0/1 -> SS half-tile (128x64, triangular ti<=tj, mirror direct).
//   r%3==2   -> m=r/3: m<16 ST (64x64, f16x2 path), m<32 TS, m==32 TT gram.
// ---------------------------------------------------------------------------
__global__ __launch_bounds__(256, 4) void adj_fused_kernel(
    const float* __restrict__ spatial, const float* __restrict__ temporal,
    const float* __restrict__ st_w1, const float* __restrict__ st_b1,
    const float* __restrict__ st_w2, const float* __restrict__ st_b2,
    const float* __restrict__ ts_w1, const float* __restrict__ ts_b1,
    const float* __restrict__ ts_w2, const float* __restrict__ ts_b2,
    float* __restrict__ out) {
    __shared__ float pool[POOL_FLOATS];

    const int b = blockIdx.x / 108;
    const int r = blockIdx.x % 108;
    const int tid = threadIdx.x;
    const int rm = r % 3;

    if (rm != 2) {
        // ====== SS gram: 128x64 half-tile, 8x4 per thread, FFMA2 ===========
        const int s = r / 3;
        int ti = 0, rem = s;
#pragma unroll
        for (int t = 0; t < 8; t++) {
            if (rem >= 8 - ti) { rem -= 8 - ti; ti++; }
        }
        const int tj = ti + rem;
        const int cj = tj * 128 + rm * 64;

        float* As = pool;             // [32][132] k-major, 128 rows
        float* Bs = pool + 32 * 132;  // [32][68]  k-major, 64 cols

        const float* Asrc = spatial + ((size_t)b * 1024 + ti * 128) * 32;
        const float* Bsrc = spatial + ((size_t)b * 1024 + cj) * 32;
        for (int l = tid; l < 1024; l += 256) {
            const int row = l >> 3;
            const int kq = (l & 7) << 2;
            const float4 va = *(const float4*)(Asrc + row * 32 + kq);
            As[(kq + 0) * 132 + row] = va.x;
            As[(kq + 1) * 132 + row] = va.y;
            As[(kq + 2) * 132 + row] = va.z;
            As[(kq + 3) * 132 + row] = va.w;
        }
        for (int l = tid; l < 512; l += 256) {
            const int row = l >> 3;
            const int kq = (l & 7) << 2;
            const float4 vb = *(const float4*)(Bsrc + row * 32 + kq);
            Bs[(kq + 0) * 68 + row] = vb.x;
            Bs[(kq + 1) * 68 + row] = vb.y;
            Bs[(kq + 2) * 68 + row] = vb.z;
            Bs[(kq + 3) * 68 + row] = vb.w;
        }
        __syncthreads();

        const int tx = tid & 15;
        const int ty = tid >> 4;
        unsigned long long acc[8][2];
#pragma unroll
        for (int i = 0; i < 8; i++) {
            acc[i][0] = 0ull;
            acc[i][1] = 0ull;
        }

        const float* Ap = As + ty * 8;
        const unsigned long long* Bq = (const unsigned long long*)(Bs + tx * 4);
#pragma unroll
        for (int k = 0; k < 32; k++) {
            const float4 a0 = *(const float4*)(Ap + k * 132);
            const float4 a1 = *(const float4*)(Ap + k * 132 + 4);
            const unsigned long long bp0 = Bq[k * 34];
            const unsigned long long bp1 = Bq[k * 34 + 1];
            const float av[8] = {a0.x, a0.y, a0.z, a0.w,
                                 a1.x, a1.y, a1.z, a1.w};
#pragma unroll
            for (int i = 0; i < 8; i++) {
                const unsigned long long ad = pack2(av[i], av[i]);
                ffma2(acc[i][0], ad, bp0);
                ffma2(acc[i][1], ad, bp1);
            }
        }

        float v[8][4];
#pragma unroll
        for (int i = 0; i < 8; i++) {
            unpack2(v[i][0], v[i][1], acc[i][0]);
            unpack2(v[i][2], v[i][3], acc[i][1]);
#pragma unroll
            for (int j = 0; j < 4; j++)
                v[i][j] = tanh_fast(fmaxf(v[i][j], 0.f));
        }

        float* ob =
            out + ((size_t)b * 1088 + ti * 128 + ty * 8) * 1088 + cj + tx * 4;
#pragma unroll
        for (int i = 0; i < 8; i++) {
            float4 o = {v[i][0], v[i][1], v[i][2], v[i][3]};
            *(float4*)(ob + (size_t)i * 1088) = o;
        }

        if (ti == tj) return;

        float* om = out + ((size_t)b * 1088 + cj) * 1088 + ti * 128 + ty * 8;
#pragma unroll
        for (int j = 0; j < 4; j++) {
            const int col = tx * 4 + j;
            float4 lo = {v[0][j], v[1][j], v[2][j], v[3][j]};
            float4 hi = {v[4][j], v[5][j], v[6][j], v[7][j]};
            *(float4*)(om + (size_t)col * 1088) = lo;
            *(float4*)(om + (size_t)col * 1088 + 4) = hi;
        }
        return;
    }

    const int m = r / 3;
    if (m > 32) return;

    if (m == 32) {
        // ==================== TT gram: 64x64 f32 path ======================
        float* As = pool;  // [32][68]
        float* Bs = pool + 32 * 68;
        const float* Tsrc = temporal + (size_t)b * 64 * 32;
        for (int l = tid; l < 512; l += 256) {
            const int row = l >> 3;
            const int kq = (l & 7) << 2;
            const float4 v = *(const float4*)(Tsrc + row * 32 + kq);
            As[(kq + 0) * 68 + row] = v.x;
            As[(kq + 1) * 68 + row] = v.y;
            As[(kq + 2) * 68 + row] = v.z;
            As[(kq + 3) * 68 + row] = v.w;
            Bs[(kq + 0) * 68 + row] = v.x;
            Bs[(kq + 1) * 68 + row] = v.y;
            Bs[(kq + 2) * 68 + row] = v.z;
            Bs[(kq + 3) * 68 + row] = v.w;
        }
        __syncthreads();

        const int tx = tid & 15;
        const int ty = tid >> 4;
        float acc[4][4];
#pragma unroll
        for (int i = 0; i < 4; i++)
#pragma unroll
            for (int j = 0; j < 4; j++) acc[i][j] = 0.f;

        const float* ap = As + ty * 4;
        const float* bp = Bs + tx * 4;
#pragma unroll
        for (int k = 0; k < 32; k++) {
            const float4 a = *(const float4*)(ap + k * 68);
            const float4 bb = *(const float4*)(bp + k * 68);
            const float av[4] = {a.x, a.y, a.z, a.w};
            const float bv[4] = {bb.x, bb.y, bb.z, bb.w};
#pragma unroll
            for (int i = 0; i < 4; i++)
#pragma unroll
                for (int j = 0; j < 4; j++)
                    acc[i][j] = fmaf(av[i], bv[j], acc[i][j]);
        }

        float* ob =
            out + ((size_t)b * 1088 + 1024 + ty * 4) * 1088 + 1024 + tx * 4;
#pragma unroll
        for (int i = 0; i < 4; i++) {
            float4 v;
            v.x = tanh_fast(fmaxf(acc[i][0], 0.f));
            v.y = tanh_fast(fmaxf(acc[i][1], 0.f));
            v.z = tanh_fast(fmaxf(acc[i][2], 0.f));
            v.w = tanh_fast(fmaxf(acc[i][3], 0.f));
            *(float4*)(ob + (size_t)i * 1088) = v;
        }
        return;
    }

    // ==================== MLP (ST / TS): f16x2 path ========================
    __half2* ah = (__half2*)pool;                    // [32][68] dup half2
    __half2* bh = (__half2*)(pool + 2176);           // [32][36] paired half2
    float* Xs = pool + 2176 + 1152;                  // [64][36]
    float* Wt = pool + 2176 + 1152 + 2304;           // [32][36]
    __half2* swh = (__half2*)(pool + 2176 + 1152 + 2304 + 1152);  // [32]
    float* c0p = pool + 2176 + 1152 + 2304 + 1152 + 32;

    const bool isST = (m < 16);
    const float* w1 = isST ? st_w1 : ts_w1;
    const float* b1 = isST ? st_b1 : ts_b1;
    const float* w2 = isST ? st_w2 : ts_w2;
    const float* b2 = isST ? st_b2 : ts_b2;
    const float* asrc;
    const float* bsrc;
    int gi0, gj0;
    if (isST) {
        asrc = spatial + ((size_t)b * 1024 + m * 64) * 32;
        bsrc = temporal + (size_t)b * 64 * 32;
        gi0 = m * 64;
        gj0 = 1024;
    } else {
        asrc = temporal + (size_t)b * 64 * 32;
        bsrc = spatial + ((size_t)b * 1024 + (m - 16) * 64) * 32;
        gi0 = 1024;
        gj0 = (m - 16) * 64;
    }

    if (tid < 32) swh[tid] = __float2half2_rn(0.5f * w2[tid]);
    proj_pass_h2(asrc, w1, b1, Xs, Wt, ah, 0, tid);  // a' (sync covers swh)
    if (tid == 0) {
        float c = b2[0];
#pragma unroll
        for (int k = 0; k < 32; k++) c += 0.5f * w2[k];
        *c0p = c;
    }
    proj_pass_h2(bsrc, w1 + 1024, nullptr, Xs, Wt, bh, 1, tid);  // b'

    const int tx = tid & 15;  // col pairs: jp = tx*2, tx*2+1 -> cols tx*4..+3
    const int ty = tid >> 4;  // rows ty*4..+3
    __half2 acc2[4][2];
    const __half2 hz = __float2half2_rn(0.f);
#pragma unroll
    for (int i = 0; i < 4; i++) {
        acc2[i][0] = hz;
        acc2[i][1] = hz;
    }

    const __half2* ap = ah + ty * 4;
    const __half2* bp = bh + tx * 2;
#pragma unroll
    for (int k = 0; k < 32; k++) {
        const uint2 aLo = *(const uint2*)(ap + k * 68);      // rows ty*4,+1
        const uint2 aHi = *(const uint2*)(ap + k * 68 + 2);  // rows +2,+3
        const uint2 bb = *(const uint2*)(bp + k * 36);       // (b0,b1),(b2,b3)
        const __half2 w2k = swh[k];
        const unsigned au[4] = {aLo.x, aLo.y, aHi.x, aHi.y};
#pragma unroll
        for (int i = 0; i < 4; i++) {
            const __half2 ai = u2h2(au[i]);
            const __half2 t0 = u2h2(tanh2_fast(h22u(__hadd2(ai, u2h2(bb.x)))));
            const __half2 t1 = u2h2(tanh2_fast(h22u(__hadd2(ai, u2h2(bb.y)))));
            acc2[i][0] = __hfma2(t0, w2k, acc2[i][0]);
            acc2[i][1] = __hfma2(t1, w2k, acc2[i][1]);
        }
    }

    const float c0 = *c0p;
    float* ob = out + ((size_t)b * 1088 + gi0 + ty * 4) * 1088 + gj0 + tx * 4;
#pragma unroll
    for (int i = 0; i < 4; i++) {
        const float2 f0 = __half22float2(acc2[i][0]);
        const float2 f1 = __half22float2(acc2[i][1]);
        float4 v;
        v.x = tanh_fast(fmaxf(f0.x + c0, 0.f));
        v.y = tanh_fast(fmaxf(f0.y + c0, 0.f));
        v.z = tanh_fast(fmaxf(f1.x + c0, 0.f));
        v.w = tanh_fast(fmaxf(f1.y + c0, 0.f));
        *(float4*)(ob + (size_t)i * 1088) = v;
    }
}

extern "C" void kernel_launch(void* const* d_in, const int* in_sizes, int n_in,
                              void* d_out, int out_size) {
    const float* spatial = (const float*)d_in[0];   // [32,1024,32]
    const float* temporal = (const float*)d_in[1];  // [32,64,32]
    const float* st_w1 = (const float*)d_in[2];     // [64,32]
    const float* st_b1 = (const float*)d_in[3];     // [32]
    const float* st_w2 = (const float*)d_in[4];     // [32,1]
    const float* st_b2 = (const float*)d_in[5];     // [1]
    const float* ts_w1 = (const float*)d_in[6];
    const float* ts_b1 = (const float*)d_in[7];
    const float* ts_w2 = (const float*)d_in[8];
    const float* ts_b2 = (const float*)d_in[9];
    float* out = (float*)d_out;                     // [32,1088,1088]

    adj_fused_kernel<<<32 * 108, 256>>>(spatial, temporal, st_w1, st_b1, st_w2,
                                        st_b2, ts_w1, ts_b1, ts_w2, ts_b2, out);
}